// round 14
// baseline (speedup 1.0000x reference)
#include <cuda_runtime.h>
#include <cstdint>

#define NN 100000
#define DD 16
#define HH 128
#define LL 2
#define CC 10
#define PITCH 68          // 64 rows + pad

// ---------------- device scratch ----------------
__device__ float g_X  [(size_t)NN*512];   // gate-interleaved X; reused as cnf-head ping/pong after LSTM
__device__ float g_h  [NN*HH];
__device__ float g_hs [NN*HH];
__device__ float g_cs [NN*HH];
__device__ float g_BtX[LL*128*512];       // Wih^T [l][k][n] plain
__device__ float g_BtH[LL*128*512];       // Whh^T [l][k][c] gate-interleaved per k-row
__device__ float g_BtS[LL*256*128];
__device__ float g_bS [LL*128];
__device__ float g_BtM[10*128*128];

// ---------------- helpers ----------------
__device__ __forceinline__ unsigned long long pack2(float x){
    unsigned long long r; unsigned u = __float_as_uint(x);
    asm("mov.b64 %0, {%1, %1};" : "=l"(r) : "r"(u));
    return r;
}
__device__ __forceinline__ void fma2(unsigned long long &d, unsigned long long a, unsigned long long b){
    asm("fma.rn.f32x2 %0, %1, %2, %0;" : "+l"(d) : "l"(a), "l"(b));
}
__device__ __forceinline__ float2 up2(unsigned long long v){
    return make_float2(__uint_as_float((unsigned)v), __uint_as_float((unsigned)(v >> 32)));
}
// HW tanh (sm_75+): 1 MUFU. sigmoid via tanh identity: 1 MUFU + 1 FMA.
__device__ __forceinline__ float tanha(float x){ float r; asm("tanh.approx.f32 %0, %1;" : "=f"(r) : "f"(x)); return r; }
__device__ __forceinline__ float sigf(float x){ return fmaf(tanha(0.5f*x), 0.5f, 0.5f); }
__device__ __forceinline__ float tanhff(float x){ return tanha(x); }
__device__ __forceinline__ uint32_t smem_u32(const void* p){
    uint32_t a;
    asm("{ .reg .u64 t; cvta.to.shared.u64 t, %1; cvt.u32.u64 %0, t; }" : "=r"(a) : "l"(p));
    return a;
}
__device__ __forceinline__ void cp_async16(uint32_t dst, const void* src){
    asm volatile("cp.async.cg.shared.global [%0], [%1], 16;" :: "r"(dst), "l"(src));
}
#define CP_COMMIT() asm volatile("cp.async.commit_group;" ::: "memory")
#define CP_WAIT1()  asm volatile("cp.async.wait_group 1;" ::: "memory")
#define CP_WAIT0()  asm volatile("cp.async.wait_group 0;" ::: "memory")

// ---------------- prep: weight transposes ----------------
__global__ void prep_lstm_t(const float* __restrict__ Wih, const float* __restrict__ Whh,
                            float* __restrict__ BtX, float* __restrict__ BtH){
    int idx = blockIdx.x*blockDim.x + threadIdx.x;
    if (idx >= LL*128*512) return;
    int c = idx & 511;
    int k = (idx >> 9) & 127;
    int l = idx >> 16;
    BtX[idx] = Wih[(l*512 + c)*128 + k];
    int half = c >> 8;
    int r = c & 255;
    int p  = r >> 2;
    int g2 = (r >> 1) & 1;
    int e  = r & 1;
    int n = (half*2 + g2)*128 + p*2 + e;
    BtH[idx] = Whh[(l*512 + n)*128 + k];
}
__global__ void prep_sage_kernel(const float* __restrict__ Ws, const float* __restrict__ Wn,
                                 float* __restrict__ Bt){
    int idx = blockIdx.x*blockDim.x + threadIdx.x;
    if (idx >= LL*256*128) return;
    int j = idx & 127;
    int k = (idx >> 7) & 255;
    int l = idx >> 15;
    Bt[idx] = (k < 128) ? Ws[(l*128 + j)*128 + k] : Wn[(l*128 + j)*128 + (k-128)];
}
__global__ void prep_bias_kernel(const float* __restrict__ bs, const float* __restrict__ bn,
                                 float* __restrict__ bS){
    int idx = threadIdx.x;
    if (idx < LL*128) bS[idx] = bs[idx] + bn[idx];
}
__global__ void prep_mlp_kernel(const float* __restrict__ clsW, const float* __restrict__ cnfW,
                                float* __restrict__ Bt){
    int idx = blockIdx.x*blockDim.x + threadIdx.x;
    if (idx >= 10*128*128) return;
    int j = idx & 127;
    int k = (idx >> 7) & 127;
    int hd = idx >> 14;
    const float* W = (hd < 5) ? (clsW + hd*16384) : (cnfW + (hd-5)*16384);
    Bt[idx] = W[j*128 + k];
}

// ---------------- precompute X = h @ Wih^T + b, stored gate-interleaved ----------------
__global__ void __launch_bounds__(256, 2) precompute_x_kernel(
    const float* __restrict__ hsrc, const float* __restrict__ Bt,
    const float* __restrict__ bias, float* __restrict__ X)
{
    __shared__ __align__(16) float Bs[16*512];
    __shared__ __align__(16) float As[16*32];
    int tid = threadIdx.x;
    int block_row = blockIdx.x * 32;

    unsigned long long acc[8][4];
#pragma unroll
    for (int i = 0; i < 8; i++){ acc[i][0]=0ull; acc[i][1]=0ull; acc[i][2]=0ull; acc[i][3]=0ull; }

    int tr = tid >> 6;
    int tc = tid & 63;
    int jj = tc * 2;

    for (int k0 = 0; k0 < 128; k0 += 16){
        __syncthreads();
        const float4* Bg = (const float4*)(Bt + k0*512);
        float4* Bs4 = (float4*)Bs;
#pragma unroll
        for (int i = 0; i < 8; i++) Bs4[tid + i*256] = Bg[tid + i*256];
        if (tid < 128){
            int m  = tid >> 2;
            int kq = (tid & 3) * 4;
            float4 v = *(const float4*)(hsrc + (size_t)(block_row + m)*HH + k0 + kq);
            As[(kq+0)*32 + m] = v.x;
            As[(kq+1)*32 + m] = v.y;
            As[(kq+2)*32 + m] = v.z;
            As[(kq+3)*32 + m] = v.w;
        }
        __syncthreads();
#pragma unroll
        for (int k = 0; k < 16; k++){
            const float* Ak = As + k*32 + tr*8;
            float4 a0 = *(const float4*)Ak;
            float4 a1 = *(const float4*)(Ak + 4);
            const float* Bk = Bs + k*512;
            unsigned long long b0 = *(const unsigned long long*)(Bk + jj);
            unsigned long long b1 = *(const unsigned long long*)(Bk + 128 + jj);
            unsigned long long b2 = *(const unsigned long long*)(Bk + 256 + jj);
            unsigned long long b3 = *(const unsigned long long*)(Bk + 384 + jj);
            float av[8] = {a0.x,a0.y,a0.z,a0.w,a1.x,a1.y,a1.z,a1.w};
#pragma unroll
            for (int i = 0; i < 8; i++){
                unsigned long long ap = pack2(av[i]);
                fma2(acc[i][0], ap, b0);
                fma2(acc[i][1], ap, b1);
                fma2(acc[i][2], ap, b2);
                fma2(acc[i][3], ap, b3);
            }
        }
    }
    float2 bv[4];
#pragma unroll
    for (int q = 0; q < 4; q++) bv[q] = *(const float2*)(bias + q*128 + jj);
#pragma unroll
    for (int i = 0; i < 8; i++){
        size_t r = (size_t)(block_row + tr*8 + i) * 512;
#pragma unroll
        for (int q = 0; q < 4; q++){
            float2 v = up2(acc[i][q]);
            v.x += bv[q].x; v.y += bv[q].y;
            *(float2*)(X + r + (size_t)tc*8 + q*2) = v;   // [pair tc][I I F F | G G O O]
        }
    }
}

// ---------------- persistent per-layer LSTM kernel: M=64, 512 threads, 1 CTA/SM ----------------
// Flat 240-tile stream (15 timesteps x 16 tiles) over a rolling 3-buffer ring:
// the B pipeline never drains across the epilogue.
// smem: Bring[3][8][512] (48KB) | AsT[128][PITCH] (34.8KB) | cs_s[64][128] (32KB)
#define SMEM_L ((3*4096 + 128*PITCH + 64*128) * 4)
#define NTILE 240

__global__ void __launch_bounds__(512, 1) lstm_layer_kernel(
    const float* __restrict__ Xi, const int* __restrict__ nbr,
    const float* __restrict__ Bt,    // Whh^T gate-interleaved [128][512]
    float* __restrict__ hsF)
{
    extern __shared__ __align__(16) float smem[];
    float* Bring = smem;                       // 3*4096 floats
    float* AsT   = Bring + 3*4096;             // [k][m] pitch PITCH
    float* cs_s  = AsT + 128*PITCH;            // [m][128]

    const int tid = threadIdx.x;
    const int tr = tid >> 6, tc = tid & 63, jj = tc*2;
    const int base = blockIdx.x * 64;
    const uint32_t sb_ring = smem_u32(Bring);

    // prefetch global tiles 0,1 (overlaps the t=0 epilogue below)
#pragma unroll
    for (int pt = 0; pt < 2; pt++){
        const float* src = Bt + pt*4096 + tid*8;
        uint32_t dst = sb_ring + (uint32_t)(pt*16384) + tid*32;
        cp_async16(dst,      src);
        cp_async16(dst + 16, src + 4);
        CP_COMMIT();
    }

    // ---- t = 0 : hs=cs=0, epilogue only ----
#pragma unroll
    for (int i = 0; i < 8; i++){
        int m = tr*8 + i;
        int node = base + m;
        int nd = (node < NN) ? node : (NN - 1);
        const float* xp = Xi + (size_t)__ldg(&nbr[nd*DD]) * 512 + tc*8;
        float4 v0 = __ldg((const float4*)xp);
        float4 v1 = __ldg((const float4*)xp + 1);
        float c0 = sigf(v0.x) * tanhff(v1.x);
        float c1 = sigf(v0.y) * tanhff(v1.y);
        cs_s[m*128 + jj]     = c0;
        cs_s[m*128 + jj + 1] = c1;
        AsT[jj*PITCH + m]     = sigf(v1.z) * tanhff(c0);
        AsT[(jj+1)*PITCH + m] = sigf(v1.w) * tanhff(c1);
    }
    __syncthreads();

    // ---- flat tile stream: t = 1..15 ----
    unsigned long long acc[8][4];
    int t = 1;
    int bufc = 0;   // g % 3
    int bufn = 2;   // (g+2) % 3
#pragma unroll 1
    for (int g = 0; g < NTILE; g++){
        const int tile = g & 15;
        if (tile == 0){
#pragma unroll
            for (int i = 0; i < 8; i++){ acc[i][0]=0ull; acc[i][1]=0ull; acc[i][2]=0ull; acc[i][3]=0ull; }
        }
        if (g == NTILE-1) CP_WAIT0(); else CP_WAIT1();
        __syncthreads();    // tile g arrived AND buffer bufn's last reader (g-1) done
        if (g < NTILE-2){
            const int st = (g + 2) & 15;
            const float* src = Bt + st*4096 + tid*8;
            uint32_t dst = sb_ring + (uint32_t)(bufn*16384) + tid*32;
            cp_async16(dst,      src);
            cp_async16(dst + 16, src + 4);
            CP_COMMIT();
        }
        const float* Bsb = Bring + bufc*4096;
#pragma unroll
        for (int kk = 0; kk < 8; kk++){
            int k = tile*8 + kk;
            const float* Ak = AsT + k*PITCH + tr*8;
            float4 a0 = *(const float4*)Ak;
            float4 a1 = *(const float4*)(Ak + 4);
            const float* Bk = Bsb + kk*512;
            ulonglong2 bIF = *(const ulonglong2*)(Bk + tc*4);
            ulonglong2 bGO = *(const ulonglong2*)(Bk + 256 + tc*4);
            float av[8] = {a0.x,a0.y,a0.z,a0.w,a1.x,a1.y,a1.z,a1.w};
#pragma unroll
            for (int i = 0; i < 8; i++){
                unsigned long long ap = pack2(av[i]);
                fma2(acc[i][0], ap, bIF.x);
                fma2(acc[i][1], ap, bIF.y);
                fma2(acc[i][2], ap, bGO.x);
                fma2(acc[i][3], ap, bGO.y);
            }
        }
        bufc++; if (bufc == 3) bufc = 0;
        bufn++; if (bufn == 3) bufn = 0;

        if (tile == 15){
            __syncthreads();   // all GEMM reads of AsT done before epilogue overwrites it
            // ---- fused LSTM epilogue (HW tanh); next timestep's B already in flight ----
#pragma unroll
            for (int i = 0; i < 8; i++){
                int m = tr*8 + i;
                int node = base + m;
                int nd = (node < NN) ? node : (NN - 1);
                const float* xp = Xi + (size_t)__ldg(&nbr[nd*DD + t]) * 512 + tc*8;
                float4 v0 = __ldg((const float4*)xp);
                float4 v1 = __ldg((const float4*)xp + 1);
                float2 I = up2(acc[i][0]);
                float2 F = up2(acc[i][1]);
                float2 G = up2(acc[i][2]);
                float2 O = up2(acc[i][3]);
                I.x += v0.x; I.y += v0.y;
                F.x += v0.z; F.y += v0.w;
                G.x += v1.x; G.y += v1.y;
                O.x += v1.z; O.y += v1.w;
                float2 cold = *(const float2*)(cs_s + m*128 + jj);
                float c0 = sigf(F.x)*cold.x + sigf(I.x)*tanhff(G.x);
                float c1 = sigf(F.y)*cold.y + sigf(I.y)*tanhff(G.y);
                float h0 = sigf(O.x) * tanhff(c0);
                float h1 = sigf(O.y) * tanhff(c1);
                *(float2*)(cs_s + m*128 + jj) = make_float2(c0, c1);
                AsT[jj*PITCH + m]     = h0;
                AsT[(jj+1)*PITCH + m] = h1;
                if (t == DD-1 && node < NN)
                    *(float2*)(hsF + (size_t)node*HH + jj) = make_float2(h0, h1);
            }
            t++;
            // next iteration's __syncthreads orders epilogue writes before AsT reads
        }
    }
}

// ---------------- fp32 f32x2 GEMM [N,Ktot] @ Bt[Ktot][128] + bias (+relu) ----------------
__global__ void __launch_bounds__(256) gemm_bias_act_kernel(
    const float* __restrict__ A0, const float* __restrict__ A1,
    const float* __restrict__ Bt, const float* __restrict__ bias,
    float* __restrict__ Cout, int Ktot, int doRelu)
{
    __shared__ __align__(16) float Bs[16*128];
    __shared__ __align__(16) float As[16*64];
    int tid = threadIdx.x;
    int block_row = blockIdx.x * 64;
    int tr = tid >> 5;
    int tc = tid & 31;
    int jj4 = tc * 4;
    unsigned long long acc[8][2];
#pragma unroll
    for (int i = 0; i < 8; i++){ acc[i][0]=0ull; acc[i][1]=0ull; }

    for (int k0 = 0; k0 < Ktot; k0 += 16){
        __syncthreads();
        const float4* Bg = (const float4*)(Bt + k0*128);
        float4* Bs4 = (float4*)Bs;
        Bs4[tid]       = Bg[tid];
        Bs4[tid + 256] = Bg[tid + 256];
        {
            int m  = tid >> 2;
            int kq = (tid & 3) * 4;
            int krow = k0 + kq;
            int row = block_row + m;
            float4 v = make_float4(0.f, 0.f, 0.f, 0.f);
            if (row < NN){
                const float* src = (krow < 128) ? (A0 + (size_t)row*HH + krow)
                                                : (A1 + (size_t)row*HH + (krow - 128));
                v = *(const float4*)src;
            }
            As[(kq+0)*64 + m] = v.x;
            As[(kq+1)*64 + m] = v.y;
            As[(kq+2)*64 + m] = v.z;
            As[(kq+3)*64 + m] = v.w;
        }
        __syncthreads();
#pragma unroll
        for (int k = 0; k < 16; k++){
            const float* Ak = As + k*64 + tr*8;
            float4 a0 = *(const float4*)Ak;
            float4 a1 = *(const float4*)(Ak + 4);
            unsigned long long b0 = *(const unsigned long long*)(Bs + k*128 + jj4);
            unsigned long long b1 = *(const unsigned long long*)(Bs + k*128 + jj4 + 2);
            float av[8] = {a0.x,a0.y,a0.z,a0.w,a1.x,a1.y,a1.z,a1.w};
#pragma unroll
            for (int i = 0; i < 8; i++){
                unsigned long long ap = pack2(av[i]);
                fma2(acc[i][0], ap, b0);
                fma2(acc[i][1], ap, b1);
            }
        }
    }
    float2 bb0 = *(const float2*)(bias + jj4);
    float2 bb1 = *(const float2*)(bias + jj4 + 2);
#pragma unroll
    for (int i = 0; i < 8; i++){
        int row = block_row + tr*8 + i;
        if (row < NN){
            float2 v0 = up2(acc[i][0]);
            float2 v1 = up2(acc[i][1]);
            v0.x += bb0.x; v0.y += bb0.y;
            v1.x += bb1.x; v1.y += bb1.y;
            if (doRelu){
                v0.x = fmaxf(v0.x, 0.f); v0.y = fmaxf(v0.y, 0.f);
                v1.x = fmaxf(v1.x, 0.f); v1.y = fmaxf(v1.y, 0.f);
            }
            float4 o; o.x=v0.x; o.y=v0.y; o.z=v1.x; o.w=v1.y;
            *(float4*)(Cout + (size_t)row*HH + jj4) = o;
        }
    }
}

// ---------------- dual-head MLP GEMM: blockIdx selects head (pointer set) ----------------
__global__ void __launch_bounds__(256) gemm_dual_kernel(
    const float* __restrict__ Aa, const float* __restrict__ Ba,
    const float* __restrict__ ba, float* __restrict__ Ca,
    const float* __restrict__ Ab, const float* __restrict__ Bb,
    const float* __restrict__ bb, float* __restrict__ Cb,
    int gridHalf)
{
    __shared__ __align__(16) float Bs[16*128];
    __shared__ __align__(16) float As[16*64];
    const int head1 = (blockIdx.x >= gridHalf);
    const int bx = head1 ? (blockIdx.x - gridHalf) : blockIdx.x;
    const float* A0   = head1 ? Ab : Aa;
    const float* Bt   = head1 ? Bb : Ba;
    const float* bias = head1 ? bb : ba;
    float* Cout       = head1 ? Cb : Ca;

    int tid = threadIdx.x;
    int block_row = bx * 64;
    int tr = tid >> 5;
    int tc = tid & 31;
    int jj4 = tc * 4;
    unsigned long long acc[8][2];
#pragma unroll
    for (int i = 0; i < 8; i++){ acc[i][0]=0ull; acc[i][1]=0ull; }

    for (int k0 = 0; k0 < 128; k0 += 16){
        __syncthreads();
        const float4* Bg = (const float4*)(Bt + k0*128);
        float4* Bs4 = (float4*)Bs;
        Bs4[tid]       = Bg[tid];
        Bs4[tid + 256] = Bg[tid + 256];
        {
            int m  = tid >> 2;
            int kq = (tid & 3) * 4;
            int row = block_row + m;
            float4 v = make_float4(0.f, 0.f, 0.f, 0.f);
            if (row < NN)
                v = *(const float4*)(A0 + (size_t)row*HH + k0 + kq);
            As[(kq+0)*64 + m] = v.x;
            As[(kq+1)*64 + m] = v.y;
            As[(kq+2)*64 + m] = v.z;
            As[(kq+3)*64 + m] = v.w;
        }
        __syncthreads();
#pragma unroll
        for (int k = 0; k < 16; k++){
            const float* Ak = As + k*64 + tr*8;
            float4 a0 = *(const float4*)Ak;
            float4 a1 = *(const float4*)(Ak + 4);
            unsigned long long b0 = *(const unsigned long long*)(Bs + k*128 + jj4);
            unsigned long long b1 = *(const unsigned long long*)(Bs + k*128 + jj4 + 2);
            float av[8] = {a0.x,a0.y,a0.z,a0.w,a1.x,a1.y,a1.z,a1.w};
#pragma unroll
            for (int i = 0; i < 8; i++){
                unsigned long long ap = pack2(av[i]);
                fma2(acc[i][0], ap, b0);
                fma2(acc[i][1], ap, b1);
            }
        }
    }
    float2 bb0 = *(const float2*)(bias + jj4);
    float2 bb1 = *(const float2*)(bias + jj4 + 2);
#pragma unroll
    for (int i = 0; i < 8; i++){
        int row = block_row + tr*8 + i;
        if (row < NN){
            float2 v0 = up2(acc[i][0]);
            float2 v1 = up2(acc[i][1]);
            v0.x = fmaxf(v0.x + bb0.x, 0.f); v0.y = fmaxf(v0.y + bb0.y, 0.f);
            v1.x = fmaxf(v1.x + bb1.x, 0.f); v1.y = fmaxf(v1.y + bb1.y, 0.f);
            float4 o; o.x=v0.x; o.y=v0.y; o.z=v1.x; o.w=v1.y;
            *(float4*)(Cout + (size_t)row*HH + jj4) = o;
        }
    }
}

// ---------------- small output heads ----------------
__global__ void head_out_kernel(const float* __restrict__ x, const float* __restrict__ W,
                                const float* __restrict__ b, float* __restrict__ out, int Cn)
{
    int gwarp = (blockIdx.x * blockDim.x + threadIdx.x) >> 5;
    int lane  = threadIdx.x & 31;
    if (gwarp >= NN) return;
    const float* xr = x + (size_t)gwarp*HH;
    float x0 = xr[lane], x1 = xr[32+lane], x2 = xr[64+lane], x3 = xr[96+lane];
    for (int c = 0; c < Cn; c++){
        const float* w = W + c*HH;
        float s = x0*w[lane] + x1*w[32+lane] + x2*w[64+lane] + x3*w[96+lane];
        s += __shfl_xor_sync(0xffffffffu, s, 16);
        s += __shfl_xor_sync(0xffffffffu, s, 8);
        s += __shfl_xor_sync(0xffffffffu, s, 4);
        s += __shfl_xor_sync(0xffffffffu, s, 2);
        s += __shfl_xor_sync(0xffffffffu, s, 1);
        if (lane == 0) out[(size_t)gwarp*Cn + c] = s + b[c];
    }
}

// ---------------- launch ----------------
extern "C" void kernel_launch(void* const* d_in, const int* in_sizes, int n_in,
                              void* d_out, int out_size)
{
    const float* h_in   = (const float*)d_in[0];
    const int*   nbr    = (const int*)  d_in[1];
    const float* Wih    = (const float*)d_in[2];
    const float* Whh    = (const float*)d_in[3];
    const float* lstmb  = (const float*)d_in[4];
    const float* Wself  = (const float*)d_in[5];
    const float* bself  = (const float*)d_in[6];
    const float* Wneigh = (const float*)d_in[7];
    const float* bneigh = (const float*)d_in[8];
    const float* clsW   = (const float*)d_in[9];
    const float* clsb   = (const float*)d_in[10];
    const float* clsoW  = (const float*)d_in[11];
    const float* clsob  = (const float*)d_in[12];
    const float* cnfW   = (const float*)d_in[13];
    const float* cnfb   = (const float*)d_in[14];
    const float* cnfoW  = (const float*)d_in[15];
    const float* cnfob  = (const float*)d_in[16];

    float *p_X, *p_h, *p_hs, *p_cs, *p_BtX, *p_BtH, *p_BtS, *p_bS, *p_BtM;
    cudaGetSymbolAddress((void**)&p_X,   g_X);
    cudaGetSymbolAddress((void**)&p_h,   g_h);
    cudaGetSymbolAddress((void**)&p_hs,  g_hs);
    cudaGetSymbolAddress((void**)&p_cs,  g_cs);
    cudaGetSymbolAddress((void**)&p_BtX, g_BtX);
    cudaGetSymbolAddress((void**)&p_BtH, g_BtH);
    cudaGetSymbolAddress((void**)&p_BtS, g_BtS);
    cudaGetSymbolAddress((void**)&p_bS,  g_bS);
    cudaGetSymbolAddress((void**)&p_BtM, g_BtM);

    float* out   = (float*)d_out;
    float* o_out = out;
    float* h_out = out + (size_t)NN*CC;
    float* l_out = out + (size_t)NN*CC + (size_t)NN*HH;

    // cnf-head ping/pong carved from g_X (free after LSTM finishes)
    float* n0 = p_X;
    float* n1 = p_X + (size_t)NN*128;

    cudaFuncSetAttribute(lstm_layer_kernel, cudaFuncAttributeMaxDynamicSharedMemorySize, SMEM_L);

    const int xgrid = NN/32;
    const int lgrid = (NN + 63)/64;   // 1563
    const int gemm_grid = (NN + 63)/64;

    // order chosen so launch #4 = lstm_layer_kernel (ncu capture slot)
    prep_lstm_t<<<(LL*128*512 + 255)/256, 256>>>(Wih, Whh, p_BtX, p_BtH);                       // #1
    prep_sage_kernel<<<(LL*256*128 + 255)/256, 256>>>(Wself, Wneigh, p_BtS);                    // #2
    precompute_x_kernel<<<xgrid, 256>>>(h_in, p_BtX, lstmb, p_X);                               // #3
    lstm_layer_kernel<<<lgrid, 512, SMEM_L>>>(p_X, nbr, p_BtH, p_hs);                           // #4 <- profiled
    prep_bias_kernel<<<1, 256>>>(bself, bneigh, p_bS);                                          // #5
    prep_mlp_kernel<<<(10*128*128 + 255)/256, 256>>>(clsW, cnfW, p_BtM);                        // #6
    gemm_bias_act_kernel<<<gemm_grid, 256>>>(h_in, p_hs, p_BtS, p_bS, p_h, 256, 1);             // sage l0

    // layer 1
    precompute_x_kernel<<<xgrid, 256>>>(p_h, p_BtX + 128*512, lstmb + 512, p_X);
    lstm_layer_kernel<<<lgrid, 512, SMEM_L>>>(p_X, nbr, p_BtH + 128*512, p_hs);
    gemm_bias_act_kernel<<<gemm_grid, 256>>>(p_h, p_hs, p_BtS + 256*128, p_bS + 128, h_out, 256, 1);

    // dual-head MLP: cls chain (BtM 0..4, p_cs/p_hs) + cnf chain (BtM 5..9, n0/n1)
    gemm_dual_kernel<<<2*gemm_grid, 256>>>(h_out, p_BtM + 0*16384, clsb + 0*128, p_cs,
                                           h_out, p_BtM + 5*16384, cnfb + 0*128, n0, gemm_grid);
    gemm_dual_kernel<<<2*gemm_grid, 256>>>(p_cs,  p_BtM + 1*16384, clsb + 1*128, p_hs,
                                           n0,    p_BtM + 6*16384, cnfb + 1*128, n1, gemm_grid);
    gemm_dual_kernel<<<2*gemm_grid, 256>>>(p_hs,  p_BtM + 2*16384, clsb + 2*128, p_cs,
                                           n1,    p_BtM + 7*16384, cnfb + 2*128, n0, gemm_grid);
    gemm_dual_kernel<<<2*gemm_grid, 256>>>(p_cs,  p_BtM + 3*16384, clsb + 3*128, p_hs,
                                           n0,    p_BtM + 8*16384, cnfb + 3*128, n1, gemm_grid);
    gemm_dual_kernel<<<2*gemm_grid, 256>>>(p_hs,  p_BtM + 4*16384, clsb + 4*128, p_cs,
                                           n1,    p_BtM + 9*16384, cnfb + 4*128, n0, gemm_grid);

    head_out_kernel<<<(NN*32 + 255)/256, 256>>>(p_cs, clsoW, clsob, o_out, CC);
    head_out_kernel<<<(NN*32 + 255)/256, 256>>>(n0,   cnfoW, cnfob, l_out, 1);
}

// round 15
// speedup vs baseline: 1.0797x; 1.0797x over previous
#include <cuda_runtime.h>
#include <cstdint>

#define NN 100000
#define DD 16
#define HH 128
#define LL 2
#define CC 10
#define PITCH 68          // 64 rows + pad

// ---------------- device scratch ----------------
__device__ float g_X  [(size_t)NN*512];
__device__ float g_h  [NN*HH];
__device__ float g_hs [NN*HH];
__device__ float g_cs [NN*HH];
__device__ float g_BtX[LL*128*512];
__device__ float g_BtH[LL*128*512];
__device__ float g_BtS[LL*256*128];
__device__ float g_bS [LL*128];
__device__ float g_BtM[10*128*128];

// ---------------- helpers ----------------
__device__ __forceinline__ unsigned long long pack2(float x){
    unsigned long long r; unsigned u = __float_as_uint(x);
    asm("mov.b64 %0, {%1, %1};" : "=l"(r) : "r"(u));
    return r;
}
__device__ __forceinline__ void fma2(unsigned long long &d, unsigned long long a, unsigned long long b){
    asm("fma.rn.f32x2 %0, %1, %2, %0;" : "+l"(d) : "l"(a), "l"(b));
}
__device__ __forceinline__ float2 up2(unsigned long long v){
    return make_float2(__uint_as_float((unsigned)v), __uint_as_float((unsigned)(v >> 32)));
}
__device__ __forceinline__ float tanha(float x){ float r; asm("tanh.approx.f32 %0, %1;" : "=f"(r) : "f"(x)); return r; }
__device__ __forceinline__ float sigf(float x){ return fmaf(tanha(0.5f*x), 0.5f, 0.5f); }
__device__ __forceinline__ float tanhff(float x){ return tanha(x); }
__device__ __forceinline__ uint32_t smem_u32(const void* p){
    uint32_t a;
    asm("{ .reg .u64 t; cvta.to.shared.u64 t, %1; cvt.u32.u64 %0, t; }" : "=r"(a) : "l"(p));
    return a;
}
__device__ __forceinline__ void cp_async16(uint32_t dst, const void* src){
    asm volatile("cp.async.cg.shared.global [%0], [%1], 16;" :: "r"(dst), "l"(src));
}
#define CP_COMMIT() asm volatile("cp.async.commit_group;" ::: "memory")
#define CP_WAIT1()  asm volatile("cp.async.wait_group 1;" ::: "memory")
#define CP_WAIT0()  asm volatile("cp.async.wait_group 0;" ::: "memory")

// ---------------- prep: weight transposes ----------------
__global__ void prep_lstm_t(const float* __restrict__ Wih, const float* __restrict__ Whh,
                            float* __restrict__ BtX, float* __restrict__ BtH){
    int idx = blockIdx.x*blockDim.x + threadIdx.x;
    if (idx >= LL*128*512) return;
    int c = idx & 511;
    int k = (idx >> 9) & 127;
    int l = idx >> 16;
    BtX[idx] = Wih[(l*512 + c)*128 + k];
    int half = c >> 8;
    int r = c & 255;
    int p  = r >> 2;
    int g2 = (r >> 1) & 1;
    int e  = r & 1;
    int n = (half*2 + g2)*128 + p*2 + e;
    BtH[idx] = Whh[(l*512 + n)*128 + k];
}
__global__ void prep_sage_kernel(const float* __restrict__ Ws, const float* __restrict__ Wn,
                                 float* __restrict__ Bt){
    int idx = blockIdx.x*blockDim.x + threadIdx.x;
    if (idx >= LL*256*128) return;
    int j = idx & 127;
    int k = (idx >> 7) & 255;
    int l = idx >> 15;
    Bt[idx] = (k < 128) ? Ws[(l*128 + j)*128 + k] : Wn[(l*128 + j)*128 + (k-128)];
}
__global__ void prep_bias_kernel(const float* __restrict__ bs, const float* __restrict__ bn,
                                 float* __restrict__ bS){
    int idx = threadIdx.x;
    if (idx < LL*128) bS[idx] = bs[idx] + bn[idx];
}
__global__ void prep_mlp_kernel(const float* __restrict__ clsW, const float* __restrict__ cnfW,
                                float* __restrict__ Bt){
    int idx = blockIdx.x*blockDim.x + threadIdx.x;
    if (idx >= 10*128*128) return;
    int j = idx & 127;
    int k = (idx >> 7) & 127;
    int hd = idx >> 14;
    const float* W = (hd < 5) ? (clsW + hd*16384) : (cnfW + (hd-5)*16384);
    Bt[idx] = W[j*128 + k];
}

// ---------------- precompute X = h @ Wih^T + b, stored gate-interleaved ----------------
__global__ void __launch_bounds__(256, 2) precompute_x_kernel(
    const float* __restrict__ hsrc, const float* __restrict__ Bt,
    const float* __restrict__ bias, float* __restrict__ X)
{
    __shared__ __align__(16) float Bs[16*512];
    __shared__ __align__(16) float As[16*32];
    int tid = threadIdx.x;
    int block_row = blockIdx.x * 32;

    unsigned long long acc[8][4];
#pragma unroll
    for (int i = 0; i < 8; i++){ acc[i][0]=0ull; acc[i][1]=0ull; acc[i][2]=0ull; acc[i][3]=0ull; }

    int tr = tid >> 6;
    int tc = tid & 63;
    int jj = tc * 2;

    for (int k0 = 0; k0 < 128; k0 += 16){
        __syncthreads();
        const float4* Bg = (const float4*)(Bt + k0*512);
        float4* Bs4 = (float4*)Bs;
#pragma unroll
        for (int i = 0; i < 8; i++) Bs4[tid + i*256] = Bg[tid + i*256];
        if (tid < 128){
            int m  = tid >> 2;
            int kq = (tid & 3) * 4;
            float4 v = *(const float4*)(hsrc + (size_t)(block_row + m)*HH + k0 + kq);
            As[(kq+0)*32 + m] = v.x;
            As[(kq+1)*32 + m] = v.y;
            As[(kq+2)*32 + m] = v.z;
            As[(kq+3)*32 + m] = v.w;
        }
        __syncthreads();
#pragma unroll
        for (int k = 0; k < 16; k++){
            const float* Ak = As + k*32 + tr*8;
            float4 a0 = *(const float4*)Ak;
            float4 a1 = *(const float4*)(Ak + 4);
            const float* Bk = Bs + k*512;
            unsigned long long b0 = *(const unsigned long long*)(Bk + jj);
            unsigned long long b1 = *(const unsigned long long*)(Bk + 128 + jj);
            unsigned long long b2 = *(const unsigned long long*)(Bk + 256 + jj);
            unsigned long long b3 = *(const unsigned long long*)(Bk + 384 + jj);
            float av[8] = {a0.x,a0.y,a0.z,a0.w,a1.x,a1.y,a1.z,a1.w};
#pragma unroll
            for (int i = 0; i < 8; i++){
                unsigned long long ap = pack2(av[i]);
                fma2(acc[i][0], ap, b0);
                fma2(acc[i][1], ap, b1);
                fma2(acc[i][2], ap, b2);
                fma2(acc[i][3], ap, b3);
            }
        }
    }
    float2 bv[4];
#pragma unroll
    for (int q = 0; q < 4; q++) bv[q] = *(const float2*)(bias + q*128 + jj);
#pragma unroll
    for (int i = 0; i < 8; i++){
        size_t r = (size_t)(block_row + tr*8 + i) * 512;
#pragma unroll
        for (int q = 0; q < 4; q++){
            float2 v = up2(acc[i][q]);
            v.x += bv[q].x; v.y += bv[q].y;
            *(float2*)(X + r + (size_t)tc*8 + q*2) = v;
        }
    }
}

// ---------------- persistent per-layer LSTM kernel (round-13 winner, unchanged) ----------------
#define SMEM_L ((3*4096 + 128*PITCH + 64*128) * 4)

__global__ void __launch_bounds__(512, 1) lstm_layer_kernel(
    const float* __restrict__ Xi, const int* __restrict__ nbr,
    const float* __restrict__ Bt,
    float* __restrict__ hsF)
{
    extern __shared__ __align__(16) float smem[];
    float* Bring = smem;
    float* AsT   = Bring + 3*4096;
    float* cs_s  = AsT + 128*PITCH;

    const int tid = threadIdx.x;
    const int tr = tid >> 6, tc = tid & 63, jj = tc*2;
    const int base = blockIdx.x * 64;
    const uint32_t sb_ring = smem_u32(Bring);

    // ---- t = 0 ----
#pragma unroll
    for (int i = 0; i < 8; i++){
        int m = tr*8 + i;
        int node = base + m;
        int nd = (node < NN) ? node : (NN - 1);
        const float* xp = Xi + (size_t)__ldg(&nbr[nd*DD]) * 512 + tc*8;
        float4 v0 = __ldg((const float4*)xp);
        float4 v1 = __ldg((const float4*)xp + 1);
        float c0 = sigf(v0.x) * tanhff(v1.x);
        float c1 = sigf(v0.y) * tanhff(v1.y);
        cs_s[m*128 + jj]     = c0;
        cs_s[m*128 + jj + 1] = c1;
        AsT[jj*PITCH + m]     = sigf(v1.z) * tanhff(c0);
        AsT[(jj+1)*PITCH + m] = sigf(v1.w) * tanhff(c1);
    }
    __syncthreads();

    // ---- t = 1..15 ----
    for (int t = 1; t < DD; t++){
        unsigned long long acc[8][4];
#pragma unroll
        for (int i = 0; i < 8; i++){ acc[i][0]=0ull; acc[i][1]=0ull; acc[i][2]=0ull; acc[i][3]=0ull; }

#pragma unroll
        for (int pt = 0; pt < 2; pt++){
            const float* src = Bt + pt*4096 + tid*8;
            uint32_t dst = sb_ring + (uint32_t)(pt*16384) + tid*32;
            cp_async16(dst,      src);
            cp_async16(dst + 16, src + 4);
            CP_COMMIT();
        }

        for (int tile = 0; tile < 16; tile++){
            if (tile == 15) CP_WAIT0(); else CP_WAIT1();
            __syncthreads();
            if (tile < 14){
                int nt = tile + 2;
                const float* src = Bt + nt*4096 + tid*8;
                uint32_t dst = sb_ring + (uint32_t)((nt % 3)*16384) + tid*32;
                cp_async16(dst,      src);
                cp_async16(dst + 16, src + 4);
                CP_COMMIT();
            }
            const float* Bsb = Bring + (tile % 3) * 4096;
#pragma unroll
            for (int kk = 0; kk < 8; kk++){
                int k = tile*8 + kk;
                const float* Ak = AsT + k*PITCH + tr*8;
                float4 a0 = *(const float4*)Ak;
                float4 a1 = *(const float4*)(Ak + 4);
                const float* Bk = Bsb + kk*512;
                ulonglong2 bIF = *(const ulonglong2*)(Bk + tc*4);
                ulonglong2 bGO = *(const ulonglong2*)(Bk + 256 + tc*4);
                float av[8] = {a0.x,a0.y,a0.z,a0.w,a1.x,a1.y,a1.z,a1.w};
#pragma unroll
                for (int i = 0; i < 8; i++){
                    unsigned long long ap = pack2(av[i]);
                    fma2(acc[i][0], ap, bIF.x);
                    fma2(acc[i][1], ap, bIF.y);
                    fma2(acc[i][2], ap, bGO.x);
                    fma2(acc[i][3], ap, bGO.y);
                }
            }
        }
        __syncthreads();

        // ---- fused LSTM epilogue (HW tanh) ----
#pragma unroll
        for (int i = 0; i < 8; i++){
            int m = tr*8 + i;
            int node = base + m;
            int nd = (node < NN) ? node : (NN - 1);
            const float* xp = Xi + (size_t)__ldg(&nbr[nd*DD + t]) * 512 + tc*8;
            float4 v0 = __ldg((const float4*)xp);
            float4 v1 = __ldg((const float4*)xp + 1);
            float2 I = up2(acc[i][0]);
            float2 F = up2(acc[i][1]);
            float2 G = up2(acc[i][2]);
            float2 O = up2(acc[i][3]);
            I.x += v0.x; I.y += v0.y;
            F.x += v0.z; F.y += v0.w;
            G.x += v1.x; G.y += v1.y;
            O.x += v1.z; O.y += v1.w;
            float2 cold = *(const float2*)(cs_s + m*128 + jj);
            float c0 = sigf(F.x)*cold.x + sigf(I.x)*tanhff(G.x);
            float c1 = sigf(F.y)*cold.y + sigf(I.y)*tanhff(G.y);
            float h0 = sigf(O.x) * tanhff(c0);
            float h1 = sigf(O.y) * tanhff(c1);
            *(float2*)(cs_s + m*128 + jj) = make_float2(c0, c1);
            AsT[jj*PITCH + m]     = h0;
            AsT[(jj+1)*PITCH + m] = h1;
            if (t == DD-1 && node < NN)
                *(float2*)(hsF + (size_t)node*HH + jj) = make_float2(h0, h1);
        }
        __syncthreads();
    }
}

// ---------------- fp32 f32x2 GEMM [N,Ktot] @ Bt[Ktot][128] + bias (+relu) ----------------
__global__ void __launch_bounds__(256) gemm_bias_act_kernel(
    const float* __restrict__ A0, const float* __restrict__ A1,
    const float* __restrict__ Bt, const float* __restrict__ bias,
    float* __restrict__ Cout, int Ktot, int doRelu)
{
    __shared__ __align__(16) float Bs[16*128];
    __shared__ __align__(16) float As[16*64];
    int tid = threadIdx.x;
    int block_row = blockIdx.x * 64;
    int tr = tid >> 5;
    int tc = tid & 31;
    int jj4 = tc * 4;
    unsigned long long acc[8][2];
#pragma unroll
    for (int i = 0; i < 8; i++){ acc[i][0]=0ull; acc[i][1]=0ull; }

    for (int k0 = 0; k0 < Ktot; k0 += 16){
        __syncthreads();
        const float4* Bg = (const float4*)(Bt + k0*128);
        float4* Bs4 = (float4*)Bs;
        Bs4[tid]       = Bg[tid];
        Bs4[tid + 256] = Bg[tid + 256];
        {
            int m  = tid >> 2;
            int kq = (tid & 3) * 4;
            int krow = k0 + kq;
            int row = block_row + m;
            float4 v = make_float4(0.f, 0.f, 0.f, 0.f);
            if (row < NN){
                const float* src = (krow < 128) ? (A0 + (size_t)row*HH + krow)
                                                : (A1 + (size_t)row*HH + (krow - 128));
                v = *(const float4*)src;
            }
            As[(kq+0)*64 + m] = v.x;
            As[(kq+1)*64 + m] = v.y;
            As[(kq+2)*64 + m] = v.z;
            As[(kq+3)*64 + m] = v.w;
        }
        __syncthreads();
#pragma unroll
        for (int k = 0; k < 16; k++){
            const float* Ak = As + k*64 + tr*8;
            float4 a0 = *(const float4*)Ak;
            float4 a1 = *(const float4*)(Ak + 4);
            unsigned long long b0 = *(const unsigned long long*)(Bs + k*128 + jj4);
            unsigned long long b1 = *(const unsigned long long*)(Bs + k*128 + jj4 + 2);
            float av[8] = {a0.x,a0.y,a0.z,a0.w,a1.x,a1.y,a1.z,a1.w};
#pragma unroll
            for (int i = 0; i < 8; i++){
                unsigned long long ap = pack2(av[i]);
                fma2(acc[i][0], ap, b0);
                fma2(acc[i][1], ap, b1);
            }
        }
    }
    float2 bb0 = *(const float2*)(bias + jj4);
    float2 bb1 = *(const float2*)(bias + jj4 + 2);
#pragma unroll
    for (int i = 0; i < 8; i++){
        int row = block_row + tr*8 + i;
        if (row < NN){
            float2 v0 = up2(acc[i][0]);
            float2 v1 = up2(acc[i][1]);
            v0.x += bb0.x; v0.y += bb0.y;
            v1.x += bb1.x; v1.y += bb1.y;
            if (doRelu){
                v0.x = fmaxf(v0.x, 0.f); v0.y = fmaxf(v0.y, 0.f);
                v1.x = fmaxf(v1.x, 0.f); v1.y = fmaxf(v1.y, 0.f);
            }
            float4 o; o.x=v0.x; o.y=v0.y; o.z=v1.x; o.w=v1.y;
            *(float4*)(Cout + (size_t)row*HH + jj4) = o;
        }
    }
}

// ---------------- persistent fused MLP heads: 5 layers + output, activations resident ----------------
// grid = 2*gridHalf (head = blockIdx half). Per CTA: 64 nodes, actT[128][68] in smem (in-place),
// B streamed via 2-buffer cp.async ring (8KB tiles), final projection from register accumulators.
#define SMEM_M ((2*2048 + 128*PITCH) * 4)

__global__ void __launch_bounds__(256, 2) mlp_head_kernel(
    const float* __restrict__ A0,      // h_out [N][128]
    const float* __restrict__ BtM,     // [10][128][128]
    const float* __restrict__ clsb, const float* __restrict__ cnfb,
    const float* __restrict__ clsoW, const float* __restrict__ clsob,
    const float* __restrict__ cnfoW, const float* __restrict__ cnfob,
    float* __restrict__ o_out, float* __restrict__ l_out, int gridHalf)
{
    extern __shared__ __align__(16) float smem[];
    float* Bs   = smem;                 // 2*2048 floats
    float* actT = smem + 4096;          // [k][m] pitch PITCH

    const int head1 = (blockIdx.x >= gridHalf);
    const int bx = head1 ? (blockIdx.x - gridHalf) : blockIdx.x;
    const float* Bbase = BtM + (head1 ? 5*16384 : 0);
    const float* bias  = head1 ? cnfb : clsb;
    const int base = bx * 64;

    const int tid = threadIdx.x;
    const int tr = tid >> 5, tc = tid & 31, jj4 = tc*4;
    const uint32_t sb = smem_u32(Bs);

    // prefetch B tile g=0
    {
        const float* src = Bbase + tid*8;
        uint32_t dst = sb + tid*32;
        cp_async16(dst, src); cp_async16(dst + 16, src + 4);
        CP_COMMIT();
    }

    // stage A transposed: thread t -> row m = t>>2, k-range (t&3)*32..+32
    {
        int m  = tid >> 2;
        int kq = (tid & 3) * 32;
        int row = base + m;
        const float* ap = A0 + (size_t)row*HH + kq;
#pragma unroll
        for (int q = 0; q < 8; q++){
            float4 v = (row < NN) ? __ldg((const float4*)(ap + q*4))
                                  : make_float4(0.f,0.f,0.f,0.f);
            int k0 = kq + q*4;
            actT[(k0+0)*PITCH + m] = v.x;
            actT[(k0+1)*PITCH + m] = v.y;
            actT[(k0+2)*PITCH + m] = v.z;
            actT[(k0+3)*PITCH + m] = v.w;
        }
    }
    __syncthreads();

    float vlast[8][4];

    for (int l = 0; l < 5; l++){
        unsigned long long acc[8][2];
#pragma unroll
        for (int i = 0; i < 8; i++){ acc[i][0]=0ull; acc[i][1]=0ull; }

        for (int tt = 0; tt < 8; tt++){
            int g = l*8 + tt;
            CP_WAIT0();
            __syncthreads();          // tile g arrived; buffer (g+1)&1's last reader done
            if (g + 1 < 40){
                const float* src = Bbase + (g+1)*2048 + tid*8;
                uint32_t dst = sb + (uint32_t)(((g+1)&1)*8192) + tid*32;
                cp_async16(dst, src); cp_async16(dst + 16, src + 4);
                CP_COMMIT();
            }
            const float* Bt0 = Bs + (g & 1) * 2048;
#pragma unroll
            for (int kk = 0; kk < 16; kk++){
                int k = tt*16 + kk;
                const float* Ak = actT + k*PITCH + tr*8;
                float4 a0 = *(const float4*)Ak;
                float4 a1 = *(const float4*)(Ak + 4);
                unsigned long long b0 = *(const unsigned long long*)(Bt0 + kk*128 + jj4);
                unsigned long long b1 = *(const unsigned long long*)(Bt0 + kk*128 + jj4 + 2);
                float av[8] = {a0.x,a0.y,a0.z,a0.w,a1.x,a1.y,a1.z,a1.w};
#pragma unroll
                for (int i = 0; i < 8; i++){
                    unsigned long long ap = pack2(av[i]);
                    fma2(acc[i][0], ap, b0);
                    fma2(acc[i][1], ap, b1);
                }
            }
        }
        __syncthreads();   // all reads of actT done before in-place overwrite

        float4 bb = __ldg((const float4*)(bias + l*128 + jj4));
#pragma unroll
        for (int i = 0; i < 8; i++){
            float2 v0 = up2(acc[i][0]);
            float2 v1 = up2(acc[i][1]);
            vlast[i][0] = fmaxf(v0.x + bb.x, 0.f);
            vlast[i][1] = fmaxf(v0.y + bb.y, 0.f);
            vlast[i][2] = fmaxf(v1.x + bb.z, 0.f);
            vlast[i][3] = fmaxf(v1.y + bb.w, 0.f);
        }
        if (l < 4){
#pragma unroll
            for (int i = 0; i < 8; i++){
                int m = tr*8 + i;
                actT[(jj4+0)*PITCH + m] = vlast[i][0];
                actT[(jj4+1)*PITCH + m] = vlast[i][1];
                actT[(jj4+2)*PITCH + m] = vlast[i][2];
                actT[(jj4+3)*PITCH + m] = vlast[i][3];
            }
            __syncthreads();
        }
    }

    // final projection from register accumulators; warp tr owns rows tr*8..+8
    const float* oW = head1 ? cnfoW : clsoW;
    const float* ob = head1 ? cnfob : clsob;
    const int Cn = head1 ? 1 : CC;
    for (int c = 0; c < Cn; c++){
        float4 w = __ldg((const float4*)(oW + c*HH + jj4));
        float obc = __ldg(ob + c);
#pragma unroll
        for (int i = 0; i < 8; i++){
            float p = vlast[i][0]*w.x + vlast[i][1]*w.y + vlast[i][2]*w.z + vlast[i][3]*w.w;
            p += __shfl_xor_sync(0xffffffffu, p, 16);
            p += __shfl_xor_sync(0xffffffffu, p, 8);
            p += __shfl_xor_sync(0xffffffffu, p, 4);
            p += __shfl_xor_sync(0xffffffffu, p, 2);
            p += __shfl_xor_sync(0xffffffffu, p, 1);
            if (tc == 0){
                int node = base + tr*8 + i;
                if (node < NN){
                    if (head1) l_out[node]         = p + obc;
                    else       o_out[node*CC + c]  = p + obc;
                }
            }
        }
    }
}

// ---------------- launch ----------------
extern "C" void kernel_launch(void* const* d_in, const int* in_sizes, int n_in,
                              void* d_out, int out_size)
{
    const float* h_in   = (const float*)d_in[0];
    const int*   nbr    = (const int*)  d_in[1];
    const float* Wih    = (const float*)d_in[2];
    const float* Whh    = (const float*)d_in[3];
    const float* lstmb  = (const float*)d_in[4];
    const float* Wself  = (const float*)d_in[5];
    const float* bself  = (const float*)d_in[6];
    const float* Wneigh = (const float*)d_in[7];
    const float* bneigh = (const float*)d_in[8];
    const float* clsW   = (const float*)d_in[9];
    const float* clsb   = (const float*)d_in[10];
    const float* clsoW  = (const float*)d_in[11];
    const float* clsob  = (const float*)d_in[12];
    const float* cnfW   = (const float*)d_in[13];
    const float* cnfb   = (const float*)d_in[14];
    const float* cnfoW  = (const float*)d_in[15];
    const float* cnfob  = (const float*)d_in[16];

    float *p_X, *p_h, *p_hs, *p_cs, *p_BtX, *p_BtH, *p_BtS, *p_bS, *p_BtM;
    cudaGetSymbolAddress((void**)&p_X,   g_X);
    cudaGetSymbolAddress((void**)&p_h,   g_h);
    cudaGetSymbolAddress((void**)&p_hs,  g_hs);
    cudaGetSymbolAddress((void**)&p_cs,  g_cs);
    cudaGetSymbolAddress((void**)&p_BtX, g_BtX);
    cudaGetSymbolAddress((void**)&p_BtH, g_BtH);
    cudaGetSymbolAddress((void**)&p_BtS, g_BtS);
    cudaGetSymbolAddress((void**)&p_bS,  g_bS);
    cudaGetSymbolAddress((void**)&p_BtM, g_BtM);

    float* out   = (float*)d_out;
    float* o_out = out;
    float* h_out = out + (size_t)NN*CC;
    float* l_out = out + (size_t)NN*CC + (size_t)NN*HH;

    cudaFuncSetAttribute(lstm_layer_kernel, cudaFuncAttributeMaxDynamicSharedMemorySize, SMEM_L);
    cudaFuncSetAttribute(mlp_head_kernel,  cudaFuncAttributeMaxDynamicSharedMemorySize, SMEM_M);

    const int xgrid = NN/32;
    const int lgrid = (NN + 63)/64;   // 1563
    const int gemm_grid = (NN + 63)/64;

    // order chosen so launch #4 = lstm_layer_kernel (ncu capture slot)
    prep_lstm_t<<<(LL*128*512 + 255)/256, 256>>>(Wih, Whh, p_BtX, p_BtH);                       // #1
    prep_sage_kernel<<<(LL*256*128 + 255)/256, 256>>>(Wself, Wneigh, p_BtS);                    // #2
    precompute_x_kernel<<<xgrid, 256>>>(h_in, p_BtX, lstmb, p_X);                               // #3
    lstm_layer_kernel<<<lgrid, 512, SMEM_L>>>(p_X, nbr, p_BtH, p_hs);                           // #4 <- profiled
    prep_bias_kernel<<<1, 256>>>(bself, bneigh, p_bS);                                          // #5
    prep_mlp_kernel<<<(10*128*128 + 255)/256, 256>>>(clsW, cnfW, p_BtM);                        // #6
    gemm_bias_act_kernel<<<gemm_grid, 256>>>(h_in, p_hs, p_BtS, p_bS, p_h, 256, 1);             // sage l0

    // layer 1
    precompute_x_kernel<<<xgrid, 256>>>(p_h, p_BtX + 128*512, lstmb + 512, p_X);
    lstm_layer_kernel<<<lgrid, 512, SMEM_L>>>(p_X, nbr, p_BtH + 128*512, p_hs);
    gemm_bias_act_kernel<<<gemm_grid, 256>>>(p_h, p_hs, p_BtS + 256*128, p_bS + 128, h_out, 256, 1);

    // fused dual-head MLP (5 layers + output projections, activations resident in smem)
    mlp_head_kernel<<<2*gemm_grid, 256, SMEM_M>>>(h_out, p_BtM, clsb, cnfb,
                                                  clsoW, clsob, cnfoW, cnfob,
                                                  o_out, l_out, gemm_grid);
}